// round 14
// baseline (speedup 1.0000x reference)
#include <cuda_runtime.h>
#include <cstdint>

#define N_NODES_C  500000
#define N_EDGES_C  8000000
#define N_GRAPHS_C 1000

#define LOG2E_F 1.4426950408889634f
#define SALPHA_F 1.7580993408473766f          // scale*alpha
#define SLN2_F   0.7282895255054788f          // scale*ln(2)

// Scratch (no cudaMalloc allowed)
__device__ float d_eon[N_NODES_C];
__device__ float d_g[N_GRAPHS_C * 8];         // per-graph: x-sum, hid-sum[5], count, pad
__device__ __align__(16) float d_EW[96];      // folded edge-stage weights (exp2-space)
__device__ __align__(16) float d_NW[64];      // folded node-stage weights (exp2-space)
__device__ unsigned int d_done;               // last-block ticket

__device__ __forceinline__ float ex2(float y) {
    float r;
    asm("ex2.approx.f32 %0, %1;" : "=f"(r) : "f"(y));
    return r;
}
// selu from y = x*log2(e):  selu(x) = s*ln2*max(y,0) + s*a*(2^min(y,0) - 1)
__device__ __forceinline__ float selu_y(float y) {
    float e   = ex2(fminf(y, 0.0f));
    float lin = fmaxf(y, 0.0f);
    return fmaf(SALPHA_F, e, fmaf(SLN2_F, lin, -SALPHA_F));
}

// ---------------------------------------------------------------------------
// Fused: zero scratch (all blocks) + fold edge/node weights (block 0).
// d_EW: [0:20) pn_w1*L  [20:30) pn_b1*L  [30:80) M*L  [80:85) d*L
//       [85:90) ue_w1[0,:]*L  [90:95) ue_w2  [95] ue_b2
// d_NW: [0:5) pe_w1*L  [5:10) pe_b1*L  [10:35) M2*L (pe_w2@un_w1[1:])
//       [35:40) D2*L   [40:45) un_w1[0,:]*L  [45:50) un_w2  [50] un_b2
// ---------------------------------------------------------------------------
__global__ void zero_and_setup(
        const float* __restrict__ pn_w1, const float* __restrict__ pn_b1,
        const float* __restrict__ pn_w2, const float* __restrict__ pn_b2,
        const float* __restrict__ ue_w1, const float* __restrict__ ue_b1,
        const float* __restrict__ ue_w2, const float* __restrict__ ue_b2,
        const float* __restrict__ pe_w1, const float* __restrict__ pe_b1,
        const float* __restrict__ pe_w2, const float* __restrict__ pe_b2,
        const float* __restrict__ un_w1, const float* __restrict__ un_b1,
        const float* __restrict__ un_w2, const float* __restrict__ un_b2) {
    if (blockIdx.x == 0) {
        int t = threadIdx.x;
        // ---- edge-stage folds ----
        if (t < 20) d_EW[t] = pn_w1[t] * LOG2E_F;
        if (t < 10) d_EW[20 + t] = pn_b1[t] * LOG2E_F;
        if (t < 50) {
            int j = t / 5, k = t % 5;
            float m = 0.0f;
            for (int q = 0; q < 10; ++q)
                m += pn_w2[j * 10 + q] * ue_w1[(1 + q) * 5 + k];
            d_EW[30 + t] = m * LOG2E_F;
        }
        if (t < 5) {
            float dd = ue_b1[t];
            for (int q = 0; q < 10; ++q)
                dd += pn_b2[q] * ue_w1[(1 + q) * 5 + t];
            d_EW[80 + t] = dd * LOG2E_F;
            d_EW[85 + t] = ue_w1[t] * LOG2E_F;
            d_EW[90 + t] = ue_w2[t];
        }
        if (t == 0) d_EW[95] = ue_b2[0];
        // ---- node-stage folds ----
        if (t < 5) {
            d_NW[t]      = pe_w1[t] * LOG2E_F;
            d_NW[5 + t]  = pe_b1[t] * LOG2E_F;
            float dd = un_b1[t];
            for (int j = 0; j < 10; ++j)
                dd += pe_b2[j] * un_w1[(1 + j) * 5 + t];
            d_NW[35 + t] = dd * LOG2E_F;
            d_NW[40 + t] = un_w1[t] * LOG2E_F;
            d_NW[45 + t] = un_w2[t];
        }
        if (t < 25) {
            int q = t / 5, k = t % 5;
            float m = 0.0f;
            for (int j = 0; j < 10; ++j)
                m += pe_w2[q * 10 + j] * un_w1[(1 + j) * 5 + k];
            d_NW[10 + t] = m * LOG2E_F;
        }
        if (t == 0) { d_NW[50] = un_b2[0]; d_done = 0u; }
    }
    int i = blockIdx.x * blockDim.x + threadIdx.x;
    int stride = gridDim.x * blockDim.x;
    float4* p = reinterpret_cast<float4*>(d_eon);
    for (int k = i; k < N_NODES_C / 4; k += stride)
        p[k] = make_float4(0.f, 0.f, 0.f, 0.f);
    for (int k = i; k < N_GRAPHS_C * 8; k += stride)
        d_g[k] = 0.f;
}

// ---------------------------------------------------------------------------
// Edge stage (best-measured R7 body): 4 adjacent edges/thread, 8 gathers in
// flight, M in shared. 4 blocks/SM x 128 thr. Single launch, grid-stride
// over ALL quads.
// ---------------------------------------------------------------------------
__global__ __launch_bounds__(128, 4) void edge_kernel(
        const float* __restrict__ nodes, const float* __restrict__ edges,
        const int* __restrict__ senders, const int* __restrict__ receivers) {
    __shared__ __align__(16) float sM[10][8];

    int t = threadIdx.x;
    if (t < 50) sM[t / 5][t % 5] = d_EW[30 + t];

    float WA[10], WB[10], WC[10];
    float D[5], U[5], V[5], B2;
#pragma unroll
    for (int j = 0; j < 10; ++j) {
        WA[j] = __ldg(d_EW + j);
        WB[j] = __ldg(d_EW + 10 + j);
        WC[j] = __ldg(d_EW + 20 + j);
    }
#pragma unroll
    for (int q = 0; q < 5; ++q) {
        D[q] = __ldg(d_EW + 80 + q);
        U[q] = __ldg(d_EW + 85 + q);
        V[q] = __ldg(d_EW + 90 + q);
    }
    B2 = __ldg(d_EW + 95);
    __syncthreads();

    const int4*   r4p = (const int4*)receivers;
    const int4*   s4p = (const int4*)senders;
    const float4* e4p = (const float4*)edges;

    const int NQ = N_EDGES_C / 4;
    const int stride = gridDim.x * blockDim.x;
    for (int q = blockIdx.x * blockDim.x + threadIdx.x; q < NQ; q += stride) {
        int4   rr = __ldg(r4p + q);
        int4   ss = __ldg(s4p + q);
        float4 ee = __ldg(e4p + q);

        float nr0 = __ldg(nodes + rr.x);
        float ns0 = __ldg(nodes + ss.x);
        float nr1 = __ldg(nodes + rr.y);
        float ns1 = __ldg(nodes + ss.y);
        float nr2 = __ldg(nodes + rr.z);
        float ns2 = __ldg(nodes + ss.z);
        float nr3 = __ldg(nodes + rr.w);
        float ns3 = __ldg(nodes + ss.w);

        float c0[5], c1[5], c2[5], c3[5];
#pragma unroll
        for (int k = 0; k < 5; ++k) { c0[k] = D[k]; c1[k] = D[k]; c2[k] = D[k]; c3[k] = D[k]; }

#pragma unroll
        for (int j = 0; j < 10; ++j) {
            float h0 = selu_y(fmaf(nr0, WA[j], fmaf(ns0, WB[j], WC[j])));
            float h1 = selu_y(fmaf(nr1, WA[j], fmaf(ns1, WB[j], WC[j])));
            float h2 = selu_y(fmaf(nr2, WA[j], fmaf(ns2, WB[j], WC[j])));
            float h3 = selu_y(fmaf(nr3, WA[j], fmaf(ns3, WB[j], WC[j])));
            float4 m4 = *reinterpret_cast<const float4*>(&sM[j][0]);
            float  m4e = sM[j][4];
            c0[0] = fmaf(h0, m4.x, c0[0]); c1[0] = fmaf(h1, m4.x, c1[0]);
            c2[0] = fmaf(h2, m4.x, c2[0]); c3[0] = fmaf(h3, m4.x, c3[0]);
            c0[1] = fmaf(h0, m4.y, c0[1]); c1[1] = fmaf(h1, m4.y, c1[1]);
            c2[1] = fmaf(h2, m4.y, c2[1]); c3[1] = fmaf(h3, m4.y, c3[1]);
            c0[2] = fmaf(h0, m4.z, c0[2]); c1[2] = fmaf(h1, m4.z, c1[2]);
            c2[2] = fmaf(h2, m4.z, c2[2]); c3[2] = fmaf(h3, m4.z, c3[2]);
            c0[3] = fmaf(h0, m4.w, c0[3]); c1[3] = fmaf(h1, m4.w, c1[3]);
            c2[3] = fmaf(h2, m4.w, c2[3]); c3[3] = fmaf(h3, m4.w, c3[3]);
            c0[4] = fmaf(h0, m4e, c0[4]);  c1[4] = fmaf(h1, m4e, c1[4]);
            c2[4] = fmaf(h2, m4e, c2[4]);  c3[4] = fmaf(h3, m4e, c3[4]);
        }

        float ev0 = ee.x, ev1 = ee.y, ev2 = ee.z, ev3 = ee.w;
#pragma unroll
        for (int it = 0; it < 3; ++it) {
            float a0 = B2, a1 = B2, a2 = B2, a3 = B2;
#pragma unroll
            for (int k = 0; k < 5; ++k) {
                a0 = fmaf(selu_y(fmaf(ev0, U[k], c0[k])), V[k], a0);
                a1 = fmaf(selu_y(fmaf(ev1, U[k], c1[k])), V[k], a1);
                a2 = fmaf(selu_y(fmaf(ev2, U[k], c2[k])), V[k], a2);
                a3 = fmaf(selu_y(fmaf(ev3, U[k], c3[k])), V[k], a3);
            }
            ev0 = a0; ev1 = a1; ev2 = a2; ev3 = a3;
        }
        atomicAdd(&d_eon[rr.x], ev0);
        atomicAdd(&d_eon[rr.y], ev1);
        atomicAdd(&d_eon[rr.z], ev2);
        atomicAdd(&d_eon[rr.w], ev3);
    }
}

// ---------------------------------------------------------------------------
// Node stage (R11 body) + fused graph epilogue via last-block ticket.
// 3 blocks/SM x 256 => 24 warps, 51 weight regs.
// ---------------------------------------------------------------------------
__global__ __launch_bounds__(256, 3) void node_kernel(
        const float* __restrict__ nodes, const int* __restrict__ graph_ids,
        const float* __restrict__ pe_w2, const float* __restrict__ pe_b2,
        const float* __restrict__ pr_w1, const float* __restrict__ pr_b1,
        const float* __restrict__ pr_w2, const float* __restrict__ pr_b2,
        float* __restrict__ out) {
    float W[51];
#pragma unroll
    for (int i = 0; i < 51; ++i) W[i] = __ldg(d_NW + i);

    int stride = gridDim.x * blockDim.x;
    for (int n = blockIdx.x * blockDim.x + threadIdx.x; n < N_NODES_C; n += stride) {
        float eon = d_eon[n];
        float hid[5];
#pragma unroll
        for (int k = 0; k < 5; ++k)
            hid[k] = selu_y(fmaf(eon, W[k], W[5 + k]));
        float c[5];
#pragma unroll
        for (int k = 0; k < 5; ++k) {
            float acc = W[35 + k];
#pragma unroll
            for (int q = 0; q < 5; ++q)
                acc = fmaf(hid[q], W[10 + q * 5 + k], acc);
            c[k] = acc;
        }
        float x = nodes[n];
#pragma unroll
        for (int it = 0; it < 3; ++it) {
            float acc = W[50];
#pragma unroll
            for (int k = 0; k < 5; ++k)
                acc = fmaf(selu_y(fmaf(x, W[40 + k], c[k])), W[45 + k], acc);
            x = acc;
        }

        float v[7];
        v[0] = x;
#pragma unroll
        for (int k = 0; k < 5; ++k) v[1 + k] = hid[k];
        v[6] = 1.0f;

        int gid = graph_ids[n];
        const unsigned mask = 0xffffffffu;
        int g0 = __shfl_sync(mask, gid, 0);
        bool uni = __all_sync(mask, gid == g0);
        if (uni) {
#pragma unroll
            for (int j = 0; j < 7; ++j) {
                float vv = v[j];
#pragma unroll
                for (int off = 16; off > 0; off >>= 1)
                    vv += __shfl_down_sync(mask, vv, off);
                if ((threadIdx.x & 31) == 0) atomicAdd(&d_g[g0 * 8 + j], vv);
            }
        } else {
#pragma unroll
            for (int j = 0; j < 7; ++j)
                atomicAdd(&d_g[gid * 8 + j], v[j]);
        }
    }

    // ---- last-block graph epilogue ----
    __shared__ unsigned s_ticket;
    __threadfence();
    __syncthreads();
    if (threadIdx.x == 0) s_ticket = atomicAdd(&d_done, 1u);
    __syncthreads();
    if (s_ticket != gridDim.x - 1) return;

    __shared__ float sPE2[50], sPEB[10];
    __shared__ float sW1[110], sB1[10], sW2[100], sB2[10];
    int t = threadIdx.x;
    if (t < 50)  sPE2[t] = pe_w2[t];
    if (t < 10)  sPEB[t] = pe_b2[t];
    if (t < 110) sW1[t] = pr_w1[t] * LOG2E_F;
    if (t < 10)  sB1[t] = pr_b1[t] * LOG2E_F;
    if (t < 100) sW2[t] = pr_w2[t] * LOG2E_F;
    if (t < 10)  sB2[t] = pr_b2[t] * LOG2E_F;
    __syncthreads();

    for (int g = t; g < N_GRAPHS_C; g += 256) {
        float gv[11];
        gv[0] = d_g[g * 8 + 0];
        float hs[5], cnt = d_g[g * 8 + 6];
#pragma unroll
        for (int q = 0; q < 5; ++q) hs[q] = d_g[g * 8 + 1 + q];
#pragma unroll
        for (int j = 0; j < 10; ++j) {
            float acc = cnt * sPEB[j];
#pragma unroll
            for (int q = 0; q < 5; ++q) acc = fmaf(hs[q], sPE2[q * 10 + j], acc);
            gv[1 + j] = acc;
        }

        float hid[10];
#pragma unroll
        for (int j = 0; j < 10; ++j) {
            float acc = sB1[j];
#pragma unroll
            for (int i = 0; i < 11; ++i) acc = fmaf(gv[i], sW1[i * 10 + j], acc);
            hid[j] = selu_y(acc);
        }
        float o[10];
        float mx = -1e30f;
#pragma unroll
        for (int k = 0; k < 10; ++k) {
            float acc = sB2[k];
#pragma unroll
            for (int j = 0; j < 10; ++j) acc = fmaf(hid[j], sW2[j * 10 + k], acc);
            o[k] = acc;
            mx = fmaxf(mx, acc);
        }
        float sum = 0.0f;
#pragma unroll
        for (int k = 0; k < 10; ++k) { o[k] = ex2(o[k] - mx); sum += o[k]; }
        float inv = 1.0f / sum;
#pragma unroll
        for (int k = 0; k < 10; ++k) out[g * 10 + k] = o[k] * inv;
    }
}

// ---------------------------------------------------------------------------
extern "C" void kernel_launch(void* const* d_in, const int* in_sizes, int n_in,
                              void* d_out, int out_size) {
    const float* nodes = (const float*)d_in[0];
    const float* edges = (const float*)d_in[1];
    const int *senders, *receivers, *graph_ids;
    const float* w[20];

    if (in_sizes[2] == N_EDGES_C) {
        senders   = (const int*)d_in[2];
        receivers = (const int*)d_in[3];
        graph_ids = (const int*)d_in[4];
        int base = (n_in > 25 && in_sizes[5] == 1) ? 6 : 5;
        for (int i = 0; i < 20; ++i) w[i] = (const float*)d_in[base + i];
    } else {
        for (int i = 0; i < 20; ++i) w[i] = (const float*)d_in[2 + i];
        senders   = (const int*)d_in[22];
        receivers = (const int*)d_in[23];
        graph_ids = (const int*)d_in[24];
    }

    zero_and_setup<<<232, 256>>>(w[0], w[1], w[2], w[3], w[4], w[5], w[6], w[7],
                                 w[8], w[9], w[10], w[11], w[12], w[13], w[14], w[15]);
    edge_kernel<<<592, 128>>>(nodes, edges, senders, receivers);
    node_kernel<<<444, 256>>>(nodes, graph_ids,
                              w[10], w[11], w[16], w[17], w[18], w[19],
                              (float*)d_out);
}

// round 15
// speedup vs baseline: 1.1441x; 1.1441x over previous
#include <cuda_runtime.h>
#include <cstdint>

#define N_NODES_C  500000
#define N_EDGES_C  8000000
#define N_GRAPHS_C 1000

#define LOG2E_F 1.4426950408889634f
#define SALPHA_F 1.7580993408473766f          // scale*alpha
#define SLN2_F   0.7282895255054788f          // scale*ln(2)

// Scratch (no cudaMalloc allowed)
__device__ float d_eon[N_NODES_C];
__device__ float d_g[N_GRAPHS_C * 8];         // per-graph: x-sum, hid-sum[5], count, pad
__device__ __align__(16) float d_EW[96];      // folded edge-stage weights (exp2-space)
__device__ __align__(16) float d_NW[64];      // folded node-stage weights (exp2-space)

__device__ __forceinline__ float ex2(float y) {
    float r;
    asm("ex2.approx.f32 %0, %1;" : "=f"(r) : "f"(y));
    return r;
}
// selu from y = x*log2(e):  selu(x) = s*ln2*max(y,0) + s*a*(2^min(y,0) - 1)
__device__ __forceinline__ float selu_y(float y) {
    float e   = ex2(fminf(y, 0.0f));
    float lin = fmaxf(y, 0.0f);
    return fmaf(SALPHA_F, e, fmaf(SLN2_F, lin, -SALPHA_F));
}

// ---------------------------------------------------------------------------
// Fused: zero scratch (all blocks) + fold edge/node weights (block 0).
// d_EW: [0:20) pn_w1*L  [20:30) pn_b1*L  [30:80) M*L  [80:85) d*L
//       [85:90) ue_w1[0,:]*L  [90:95) ue_w2  [95] ue_b2
// d_NW: [0:5) pe_w1*L  [5:10) pe_b1*L  [10:35) M2*L (pe_w2@un_w1[1:])
//       [35:40) D2*L   [40:45) un_w1[0,:]*L  [45:50) un_w2  [50] un_b2
// ---------------------------------------------------------------------------
__global__ void zero_and_setup(
        const float* __restrict__ pn_w1, const float* __restrict__ pn_b1,
        const float* __restrict__ pn_w2, const float* __restrict__ pn_b2,
        const float* __restrict__ ue_w1, const float* __restrict__ ue_b1,
        const float* __restrict__ ue_w2, const float* __restrict__ ue_b2,
        const float* __restrict__ pe_w1, const float* __restrict__ pe_b1,
        const float* __restrict__ pe_w2, const float* __restrict__ pe_b2,
        const float* __restrict__ un_w1, const float* __restrict__ un_b1,
        const float* __restrict__ un_w2, const float* __restrict__ un_b2) {
    if (blockIdx.x == 0) {
        int t = threadIdx.x;
        // ---- edge-stage folds ----
        if (t < 20) d_EW[t] = pn_w1[t] * LOG2E_F;
        if (t < 10) d_EW[20 + t] = pn_b1[t] * LOG2E_F;
        if (t < 50) {
            int j = t / 5, k = t % 5;
            float m = 0.0f;
            for (int q = 0; q < 10; ++q)
                m += pn_w2[j * 10 + q] * ue_w1[(1 + q) * 5 + k];
            d_EW[30 + t] = m * LOG2E_F;
        }
        if (t < 5) {
            float dd = ue_b1[t];
            for (int q = 0; q < 10; ++q)
                dd += pn_b2[q] * ue_w1[(1 + q) * 5 + t];
            d_EW[80 + t] = dd * LOG2E_F;
            d_EW[85 + t] = ue_w1[t] * LOG2E_F;
            d_EW[90 + t] = ue_w2[t];
        }
        if (t == 0) d_EW[95] = ue_b2[0];
        // ---- node-stage folds ----
        if (t < 5) {
            d_NW[t]      = pe_w1[t] * LOG2E_F;
            d_NW[5 + t]  = pe_b1[t] * LOG2E_F;
            float dd = un_b1[t];
            for (int j = 0; j < 10; ++j)
                dd += pe_b2[j] * un_w1[(1 + j) * 5 + t];
            d_NW[35 + t] = dd * LOG2E_F;
            d_NW[40 + t] = un_w1[t] * LOG2E_F;
            d_NW[45 + t] = un_w2[t];
        }
        if (t < 25) {
            int q = t / 5, k = t % 5;
            float m = 0.0f;
            for (int j = 0; j < 10; ++j)
                m += pe_w2[q * 10 + j] * un_w1[(1 + j) * 5 + k];
            d_NW[10 + t] = m * LOG2E_F;
        }
        if (t == 0) d_NW[50] = un_b2[0];
    }
    int i = blockIdx.x * blockDim.x + threadIdx.x;
    int stride = gridDim.x * blockDim.x;
    float4* p = reinterpret_cast<float4*>(d_eon);
    for (int k = i; k < N_NODES_C / 4; k += stride)
        p[k] = make_float4(0.f, 0.f, 0.f, 0.f);
    for (int k = i; k < N_GRAPHS_C * 8; k += stride)
        d_g[k] = 0.f;
}

// ---------------------------------------------------------------------------
// Edge stage (best-measured R7 body): 4 adjacent edges/thread, 8 gathers in
// flight, M in shared. 4 blocks/SM x 128 thr. Single launch, grid-stride
// over ALL quads.
// ---------------------------------------------------------------------------
__global__ __launch_bounds__(128, 4) void edge_kernel(
        const float* __restrict__ nodes, const float* __restrict__ edges,
        const int* __restrict__ senders, const int* __restrict__ receivers) {
    __shared__ __align__(16) float sM[10][8];

    int t = threadIdx.x;
    if (t < 50) sM[t / 5][t % 5] = d_EW[30 + t];

    float WA[10], WB[10], WC[10];
    float D[5], U[5], V[5], B2;
#pragma unroll
    for (int j = 0; j < 10; ++j) {
        WA[j] = __ldg(d_EW + j);
        WB[j] = __ldg(d_EW + 10 + j);
        WC[j] = __ldg(d_EW + 20 + j);
    }
#pragma unroll
    for (int q = 0; q < 5; ++q) {
        D[q] = __ldg(d_EW + 80 + q);
        U[q] = __ldg(d_EW + 85 + q);
        V[q] = __ldg(d_EW + 90 + q);
    }
    B2 = __ldg(d_EW + 95);
    __syncthreads();

    const int4*   r4p = (const int4*)receivers;
    const int4*   s4p = (const int4*)senders;
    const float4* e4p = (const float4*)edges;

    const int NQ = N_EDGES_C / 4;
    const int stride = gridDim.x * blockDim.x;
    for (int q = blockIdx.x * blockDim.x + threadIdx.x; q < NQ; q += stride) {
        int4   rr = __ldg(r4p + q);
        int4   ss = __ldg(s4p + q);
        float4 ee = __ldg(e4p + q);

        float nr0 = __ldg(nodes + rr.x);
        float ns0 = __ldg(nodes + ss.x);
        float nr1 = __ldg(nodes + rr.y);
        float ns1 = __ldg(nodes + ss.y);
        float nr2 = __ldg(nodes + rr.z);
        float ns2 = __ldg(nodes + ss.z);
        float nr3 = __ldg(nodes + rr.w);
        float ns3 = __ldg(nodes + ss.w);

        float c0[5], c1[5], c2[5], c3[5];
#pragma unroll
        for (int k = 0; k < 5; ++k) { c0[k] = D[k]; c1[k] = D[k]; c2[k] = D[k]; c3[k] = D[k]; }

#pragma unroll
        for (int j = 0; j < 10; ++j) {
            float h0 = selu_y(fmaf(nr0, WA[j], fmaf(ns0, WB[j], WC[j])));
            float h1 = selu_y(fmaf(nr1, WA[j], fmaf(ns1, WB[j], WC[j])));
            float h2 = selu_y(fmaf(nr2, WA[j], fmaf(ns2, WB[j], WC[j])));
            float h3 = selu_y(fmaf(nr3, WA[j], fmaf(ns3, WB[j], WC[j])));
            float4 m4 = *reinterpret_cast<const float4*>(&sM[j][0]);
            float  m4e = sM[j][4];
            c0[0] = fmaf(h0, m4.x, c0[0]); c1[0] = fmaf(h1, m4.x, c1[0]);
            c2[0] = fmaf(h2, m4.x, c2[0]); c3[0] = fmaf(h3, m4.x, c3[0]);
            c0[1] = fmaf(h0, m4.y, c0[1]); c1[1] = fmaf(h1, m4.y, c1[1]);
            c2[1] = fmaf(h2, m4.y, c2[1]); c3[1] = fmaf(h3, m4.y, c3[1]);
            c0[2] = fmaf(h0, m4.z, c0[2]); c1[2] = fmaf(h1, m4.z, c1[2]);
            c2[2] = fmaf(h2, m4.z, c2[2]); c3[2] = fmaf(h3, m4.z, c3[2]);
            c0[3] = fmaf(h0, m4.w, c0[3]); c1[3] = fmaf(h1, m4.w, c1[3]);
            c2[3] = fmaf(h2, m4.w, c2[3]); c3[3] = fmaf(h3, m4.w, c3[3]);
            c0[4] = fmaf(h0, m4e, c0[4]);  c1[4] = fmaf(h1, m4e, c1[4]);
            c2[4] = fmaf(h2, m4e, c2[4]);  c3[4] = fmaf(h3, m4e, c3[4]);
        }

        float ev0 = ee.x, ev1 = ee.y, ev2 = ee.z, ev3 = ee.w;
#pragma unroll
        for (int it = 0; it < 3; ++it) {
            float a0 = B2, a1 = B2, a2 = B2, a3 = B2;
#pragma unroll
            for (int k = 0; k < 5; ++k) {
                a0 = fmaf(selu_y(fmaf(ev0, U[k], c0[k])), V[k], a0);
                a1 = fmaf(selu_y(fmaf(ev1, U[k], c1[k])), V[k], a1);
                a2 = fmaf(selu_y(fmaf(ev2, U[k], c2[k])), V[k], a2);
                a3 = fmaf(selu_y(fmaf(ev3, U[k], c3[k])), V[k], a3);
            }
            ev0 = a0; ev1 = a1; ev2 = a2; ev3 = a3;
        }
        atomicAdd(&d_eon[rr.x], ev0);
        atomicAdd(&d_eon[rr.y], ev1);
        atomicAdd(&d_eon[rr.z], ev2);
        atomicAdd(&d_eon[rr.w], ev3);
    }
}

// ---------------------------------------------------------------------------
// Node stage: ILP-2 (two grid-strided slots/thread), M2/D2 in shared,
// 3 blocks/SM x 256 => 24 warps (same as R11) with doubled chain ILP.
// Warp spans stay 32 consecutive nodes per slot (uniform fast path).
// ---------------------------------------------------------------------------
#define NILP 2
__global__ __launch_bounds__(256, 3) void node_kernel(
        const float* __restrict__ nodes, const int* __restrict__ graph_ids) {
    __shared__ float sM2[25], sD2[5];
    {
        int t = threadIdx.x;
        if (t < 25) sM2[t] = d_NW[10 + t];
        if (t < 5)  sD2[t] = d_NW[35 + t];
    }
    float PW1[5], PB1[5], U[5], V[5], B2;
#pragma unroll
    for (int k = 0; k < 5; ++k) {
        PW1[k] = __ldg(d_NW + k);
        PB1[k] = __ldg(d_NW + 5 + k);
        U[k]   = __ldg(d_NW + 40 + k);
        V[k]   = __ldg(d_NW + 45 + k);
    }
    B2 = __ldg(d_NW + 50);
    __syncthreads();

    const int T = gridDim.x * blockDim.x;
    const int n0 = blockIdx.x * blockDim.x + threadIdx.x;

    int   nn[NILP];
    bool  act[NILP];
    float eon[NILP], x[NILP];
#pragma unroll
    for (int s = 0; s < NILP; ++s) {
        int n = n0 + s * T;
        act[s] = n < N_NODES_C;
        nn[s]  = act[s] ? n : (N_NODES_C - 1);
        eon[s] = d_eon[nn[s]];
        x[s]   = nodes[nn[s]];
    }

    float hid[NILP][5];
#pragma unroll
    for (int k = 0; k < 5; ++k)
#pragma unroll
        for (int s = 0; s < NILP; ++s)
            hid[s][k] = selu_y(fmaf(eon[s], PW1[k], PB1[k]));

    float c[NILP][5];
#pragma unroll
    for (int k = 0; k < 5; ++k) {
        float d2 = sD2[k];
#pragma unroll
        for (int s = 0; s < NILP; ++s) {
            float acc = d2;
#pragma unroll
            for (int q = 0; q < 5; ++q)
                acc = fmaf(hid[s][q], sM2[q * 5 + k], acc);
            c[s][k] = acc;
        }
    }

#pragma unroll
    for (int it = 0; it < 3; ++it) {
        float a[NILP];
#pragma unroll
        for (int s = 0; s < NILP; ++s) a[s] = B2;
#pragma unroll
        for (int k = 0; k < 5; ++k)
#pragma unroll
            for (int s = 0; s < NILP; ++s)
                a[s] = fmaf(selu_y(fmaf(x[s], U[k], c[s][k])), V[k], a[s]);
#pragma unroll
        for (int s = 0; s < NILP; ++s) x[s] = a[s];
    }

    const unsigned mask = 0xffffffffu;
#pragma unroll
    for (int s = 0; s < NILP; ++s) {
        float v[7];
        float m = act[s] ? 1.0f : 0.0f;
        v[0] = x[s] * m;
#pragma unroll
        for (int k = 0; k < 5; ++k) v[1 + k] = hid[s][k] * m;
        v[6] = m;

        int gid = graph_ids[nn[s]];
        int g0 = __shfl_sync(mask, gid, 0);
        bool uni = __all_sync(mask, gid == g0);
        if (uni) {
#pragma unroll
            for (int j = 0; j < 7; ++j) {
                float vv = v[j];
#pragma unroll
                for (int off = 16; off > 0; off >>= 1)
                    vv += __shfl_down_sync(mask, vv, off);
                if ((threadIdx.x & 31) == 0) atomicAdd(&d_g[g0 * 8 + j], vv);
            }
        } else if (act[s]) {
#pragma unroll
            for (int j = 0; j < 7; ++j)
                atomicAdd(&d_g[gid * 8 + j], v[j]);
        }
    }
}

// ---------------------------------------------------------------------------
// Final: reconstruct g[11] (x-sum, cnt*pe_b2 + hidsum@pe_w2), pr MLP, softmax.
// ---------------------------------------------------------------------------
__global__ __launch_bounds__(128) void graph_kernel(
        const float* __restrict__ pe_w2, const float* __restrict__ pe_b2,
        const float* __restrict__ pr_w1, const float* __restrict__ pr_b1,
        const float* __restrict__ pr_w2, const float* __restrict__ pr_b2,
        float* __restrict__ out) {
    __shared__ float sPE2[50], sPEB[10];
    __shared__ float sW1[110], sB1[10], sW2[100], sB2[10];
    int t = threadIdx.x;
    if (t < 50)  sPE2[t] = pe_w2[t];
    if (t < 10)  sPEB[t] = pe_b2[t];
    if (t < 110) sW1[t] = pr_w1[t] * LOG2E_F;
    if (t < 10)  sB1[t] = pr_b1[t] * LOG2E_F;
    if (t < 100) sW2[t] = pr_w2[t] * LOG2E_F;
    if (t < 10)  sB2[t] = pr_b2[t] * LOG2E_F;
    __syncthreads();

    int g = blockIdx.x * blockDim.x + threadIdx.x;
    if (g >= N_GRAPHS_C) return;

    float gv[11];
    gv[0] = d_g[g * 8 + 0];
    float hs[5], cnt = d_g[g * 8 + 6];
#pragma unroll
    for (int q = 0; q < 5; ++q) hs[q] = d_g[g * 8 + 1 + q];
#pragma unroll
    for (int j = 0; j < 10; ++j) {
        float acc = cnt * sPEB[j];
#pragma unroll
        for (int q = 0; q < 5; ++q) acc = fmaf(hs[q], sPE2[q * 10 + j], acc);
        gv[1 + j] = acc;
    }

    float hid[10];
#pragma unroll
    for (int j = 0; j < 10; ++j) {
        float acc = sB1[j];
#pragma unroll
        for (int i = 0; i < 11; ++i) acc = fmaf(gv[i], sW1[i * 10 + j], acc);
        hid[j] = selu_y(acc);
    }
    float o[10];
    float mx = -1e30f;
#pragma unroll
    for (int k = 0; k < 10; ++k) {
        float acc = sB2[k];
#pragma unroll
        for (int j = 0; j < 10; ++j) acc = fmaf(hid[j], sW2[j * 10 + k], acc);
        o[k] = acc;
        mx = fmaxf(mx, acc);
    }
    float sum = 0.0f;
#pragma unroll
    for (int k = 0; k < 10; ++k) { o[k] = ex2(o[k] - mx); sum += o[k]; }
    float inv = 1.0f / sum;
#pragma unroll
    for (int k = 0; k < 10; ++k) out[g * 10 + k] = o[k] * inv;
}

// ---------------------------------------------------------------------------
extern "C" void kernel_launch(void* const* d_in, const int* in_sizes, int n_in,
                              void* d_out, int out_size) {
    const float* nodes = (const float*)d_in[0];
    const float* edges = (const float*)d_in[1];
    const int *senders, *receivers, *graph_ids;
    const float* w[20];

    if (in_sizes[2] == N_EDGES_C) {
        senders   = (const int*)d_in[2];
        receivers = (const int*)d_in[3];
        graph_ids = (const int*)d_in[4];
        int base = (n_in > 25 && in_sizes[5] == 1) ? 6 : 5;
        for (int i = 0; i < 20; ++i) w[i] = (const float*)d_in[base + i];
    } else {
        for (int i = 0; i < 20; ++i) w[i] = (const float*)d_in[2 + i];
        senders   = (const int*)d_in[22];
        receivers = (const int*)d_in[23];
        graph_ids = (const int*)d_in[24];
    }

    zero_and_setup<<<232, 256>>>(w[0], w[1], w[2], w[3], w[4], w[5], w[6], w[7],
                                 w[8], w[9], w[10], w[11], w[12], w[13], w[14], w[15]);
    edge_kernel<<<592, 128>>>(nodes, edges, senders, receivers);
    // node: ILP-2 -> T*2 >= N ; T = 250112 -> 977 blocks of 256
    node_kernel<<<977, 256>>>(nodes, graph_ids);
    graph_kernel<<<8, 128>>>(w[10], w[11], w[16], w[17], w[18], w[19], (float*)d_out);
}